// round 1
// baseline (speedup 1.0000x reference)
#include <cuda_runtime.h>
#include <math.h>

#define BQ 16
#define TT 64
#define HH 1024
#define NNDIM 4096
#define G3 3072

typedef unsigned long long u64;

// ---------- packed f32x2 helpers (FFMA2: full-rate fp32 on sm_103a) ----------
__device__ __forceinline__ u64 pk2(float lo, float hi) {
    u64 r; asm("mov.b64 %0,{%1,%2};" : "=l"(r) : "f"(lo), "f"(hi)); return r;
}
__device__ __forceinline__ float2 upk2(u64 v) {
    float2 f; asm("mov.b64 {%0,%1},%2;" : "=f"(f.x), "=f"(f.y) : "l"(v)); return f;
}
__device__ __forceinline__ void fma2(u64 &d, u64 a, u64 b) {
    asm("fma.rn.f32x2 %0,%1,%2,%0;" : "+l"(d) : "l"(a), "l"(b));
}

// ---------- device scratch (no allocations allowed) ----------
__device__ float g_gates[BQ * TT * G3];   // 12.6 MB, reused by both layers
__device__ float g_seq[BQ * TT * HH];     // 4 MB, layer-0 output sequence
__device__ float g_hbuf[2][BQ * HH];      // ping-pong hidden state
__device__ unsigned g_count = 0;
__device__ volatile unsigned g_gen = 0;

// =====================================================================
// GEMM: C[M,N] = A[M,K] @ Bw[N,K]^T + bias[N]   (all row-major, f32)
// BM=64, BN=128, BK=16, 128 threads, 8x8 microtile with f32x2 FMAs.
// Requires M%64==0, N%128==0, K%16==0 (holds for all uses here).
// =====================================================================
#define GBM 64
#define GBN 128
#define GBK 16

__global__ void __launch_bounds__(128) gemm_nt_bias(
    const float* __restrict__ A, const float* __restrict__ Bw,
    const float* __restrict__ bias, float* __restrict__ C,
    int M, int N, int K)
{
    __shared__ __align__(16) float As[GBK][GBM + 4];
    __shared__ __align__(16) float Bs[GBK][GBN + 4];

    const int tid = threadIdx.x;
    const int tn = tid & 15;        // 0..15  -> 8 cols each
    const int tm = tid >> 4;        // 0..7   -> 8 rows each
    const int m0 = blockIdx.y * GBM;
    const int n0 = blockIdx.x * GBN;

    u64 acc[8][4];
#pragma unroll
    for (int i = 0; i < 8; ++i)
#pragma unroll
        for (int j = 0; j < 4; ++j) acc[i][j] = 0ull;

    for (int k0 = 0; k0 < K; k0 += GBK) {
        // load A tile (64x16), transposed into As[k][m]
#pragma unroll
        for (int f = 0; f < 2; ++f) {
            int fid = tid + f * 128;
            int row = fid >> 2;
            int c4  = (fid & 3) * 4;
            float4 v = *(const float4*)(A + (size_t)(m0 + row) * K + k0 + c4);
            As[c4 + 0][row] = v.x; As[c4 + 1][row] = v.y;
            As[c4 + 2][row] = v.z; As[c4 + 3][row] = v.w;
        }
        // load B tile (128x16), transposed into Bs[k][n]
#pragma unroll
        for (int f = 0; f < 4; ++f) {
            int fid = tid + f * 128;
            int row = fid >> 2;
            int c4  = (fid & 3) * 4;
            float4 v = *(const float4*)(Bw + (size_t)(n0 + row) * K + k0 + c4);
            Bs[c4 + 0][row] = v.x; Bs[c4 + 1][row] = v.y;
            Bs[c4 + 2][row] = v.z; Bs[c4 + 3][row] = v.w;
        }
        __syncthreads();

#pragma unroll
        for (int kk = 0; kk < GBK; ++kk) {
            float4 aA = *(const float4*)&As[kk][tm * 8];
            float4 aB = *(const float4*)&As[kk][tm * 8 + 4];
            u64 av[8] = { pk2(aA.x, aA.x), pk2(aA.y, aA.y), pk2(aA.z, aA.z), pk2(aA.w, aA.w),
                          pk2(aB.x, aB.x), pk2(aB.y, aB.y), pk2(aB.z, aB.z), pk2(aB.w, aB.w) };
            ulonglong2 bA = *(const ulonglong2*)&Bs[kk][tn * 8];
            ulonglong2 bB = *(const ulonglong2*)&Bs[kk][tn * 8 + 4];
            u64 bv[4] = { bA.x, bA.y, bB.x, bB.y };
#pragma unroll
            for (int i = 0; i < 8; ++i)
#pragma unroll
                for (int j = 0; j < 4; ++j) fma2(acc[i][j], av[i], bv[j]);
        }
        __syncthreads();
    }

#pragma unroll
    for (int i = 0; i < 8; ++i) {
        int m = m0 + tm * 8 + i;
#pragma unroll
        for (int j = 0; j < 4; ++j) {
            int n = n0 + tn * 8 + j * 2;
            float2 v = upk2(acc[i][j]);
            float2 o;
            o.x = v.x + __ldg(bias + n);
            o.y = v.y + __ldg(bias + n + 1);
            *(float2*)(C + (size_t)m * N + n) = o;
        }
    }
}

// =====================================================================
// Persistent GRU recurrence. 128 CTAs x 256 threads, all co-resident
// (165 KB dyn smem -> 1 CTA/SM). w_hh slice lives in SMEM across all
// 64 steps; h broadcast via L2 with a software grid barrier per step.
// CTA owns 8 hidden units. Warp = 2 units x 8 batches (balances h vs w
// smem crossbar traffic). f32x2 FMAs.
// =====================================================================
#define RCTA 128
#define REC_SMEM ((24 * HH + 16 * HH + 8 * 48) * 4)

__device__ __forceinline__ void grid_barrier_dev() {
    __syncthreads();
    if (threadIdx.x == 0) {
        __threadfence();                       // publish my CTA's stores
        unsigned gen = g_gen;
        if (atomicAdd(&g_count, 1u) == (unsigned)(gridDim.x - 1)) {
            g_count = 0;
            __threadfence();
            g_gen = gen + 1;
        } else {
            while (g_gen == gen) { }
        }
        __threadfence();                       // gpu-scope fence: invalidates L1 (B300)
    }
    __syncthreads();
}

__global__ void __launch_bounds__(256, 1) gru_recurrence(
    const float* __restrict__ w_hh, const float* __restrict__ b_hh,
    const float* __restrict__ gates, float* __restrict__ seq_out,
    int write_seq)
{
    extern __shared__ __align__(16) float smem[];
    float* sW   = smem;               // [24][1024]  rows: unit-local*3 + gate
    float* sH   = smem + 24 * HH;     // [16][1024]
    float* sRed = smem + 40 * HH;     // [8][48] per-warp reduction scratch

    const int tid  = threadIdx.x;
    const int w    = tid >> 5;
    const int lane = tid & 31;
    const int ubase = blockIdx.x * 8;
    const int up = w & 3;             // unit-pair index (units up*2, up*2+1)
    const int bh = w >> 2;            // batch half (8 batches)
    const int rbase = up * 6;

    // ---- load w_hh slice to SMEM (stays for all 64 steps) ----
    for (int i = tid; i < 24 * HH / 4; i += 256) {
        int row = i >> 8;             // 0..23
        int c   = (i & 255) * 4;
        int lu  = row / 3;
        int g   = row - lu * 3;
        *(float4*)&sW[row * HH + c] =
            *(const float4*)&w_hh[(size_t)(g * HH + ubase + lu) * HH + c];
    }

    // ---- zero h0 (buffer 0) across the grid ----
    {
        int idx = blockIdx.x * 256 + tid;
        if (idx < BQ * HH) g_hbuf[0][idx] = 0.f;
    }

    // ---- per-lane epilogue constants ----
    const int ul   = (lane >> 3) & 1;
    const int bl   = lane & 7;
    const int b_ep = bh * 8 + bl;
    const int u_ep = ubase + up * 2 + ul;
    float bhr = 0.f, bhz = 0.f, bhn = 0.f;
    if (lane < 16) {
        bhr = b_hh[u_ep];
        bhz = b_hh[HH + u_ep];
        bhn = b_hh[2 * HH + u_ep];
    }

    grid_barrier_dev();   // zeros + weights visible everywhere

    for (int t = 0; t < TT; ++t) {
        const float* hsrc = g_hbuf[t & 1];
        float* hdst = g_hbuf[(t + 1) & 1];

        // prefetch this step's gates_x for the epilogue (long slack)
        float gxr = 0.f, gxz = 0.f, gxn = 0.f;
        if (lane < 16) {
            const float* gp = gates + (size_t)(b_ep * TT + t) * G3 + u_ep;
            gxr = __ldg(gp);
            gxz = __ldg(gp + HH);
            gxn = __ldg(gp + 2 * HH);
        }

        // stage h (L2-only loads: other CTAs wrote it last step)
        for (int i = tid; i < BQ * HH / 4; i += 256) {
            float4 v = __ldcg(((const float4*)hsrc) + i);
            *(((float4*)sH) + i) = v;
        }
        __syncthreads();

        // ---- main accumulation: 6 rows x 8 batches, k=1024 ----
        u64 acc[6][8];
#pragma unroll
        for (int r = 0; r < 6; ++r)
#pragma unroll
            for (int b = 0; b < 8; ++b) acc[r][b] = 0ull;

#pragma unroll
        for (int it = 0; it < 8; ++it) {
            int kq = it * 32 + lane;  // 16B-unit index (256 per 1024-float row)
            ulonglong2 hv[8];
#pragma unroll
            for (int b = 0; b < 8; ++b)
                hv[b] = *(((const ulonglong2*)(sH + (bh * 8 + b) * HH)) + kq);
#pragma unroll
            for (int r = 0; r < 6; ++r) {
                ulonglong2 wv = *(((const ulonglong2*)(sW + (rbase + r) * HH)) + kq);
#pragma unroll
                for (int b = 0; b < 8; ++b) {
                    fma2(acc[r][b], wv.x, hv[b].x);
                    fma2(acc[r][b], wv.y, hv[b].y);
                }
            }
        }

        // ---- warp reduction -> smem scratch ----
#pragma unroll
        for (int r = 0; r < 6; ++r) {
#pragma unroll
            for (int b = 0; b < 8; ++b) {
                float2 f = upk2(acc[r][b]);
                float v = f.x + f.y;
                v += __shfl_xor_sync(0xffffffffu, v, 16);
                v += __shfl_xor_sync(0xffffffffu, v, 8);
                v += __shfl_xor_sync(0xffffffffu, v, 4);
                v += __shfl_xor_sync(0xffffffffu, v, 2);
                v += __shfl_xor_sync(0xffffffffu, v, 1);
                if (lane == 0) sRed[w * 48 + r * 8 + b] = v;
            }
        }
        __syncwarp();

        // ---- GRU gate epilogue (16 lanes = 2 units x 8 batches) ----
        if (lane < 16) {
            float ghr = sRed[w * 48 + (ul * 3 + 0) * 8 + bl] + bhr;
            float ghz = sRed[w * 48 + (ul * 3 + 1) * 8 + bl] + bhz;
            float ghn = sRed[w * 48 + (ul * 3 + 2) * 8 + bl] + bhn;
            float rr = 1.f / (1.f + __expf(-(gxr + ghr)));
            float zz = 1.f / (1.f + __expf(-(gxz + ghz)));
            float nn = tanhf(gxn + rr * ghn);
            float hp = sH[b_ep * HH + u_ep];
            float hv = (1.f - zz) * nn + zz * hp;
            hdst[b_ep * HH + u_ep] = hv;
            if (write_seq)
                seq_out[(size_t)(b_ep * TT + t) * HH + u_ep] = hv;
        }

        grid_barrier_dev();
    }
}

// =====================================================================
// Decoder: out[b,n] = h[b,:] . dec_w[n,:] + dec_b[n]   (M=16,N=4096,K=1024)
// =====================================================================
__global__ void __launch_bounds__(256) decoder_kernel(
    const float* __restrict__ h, const float* __restrict__ dw,
    const float* __restrict__ db, float* __restrict__ out)
{
    extern __shared__ __align__(16) float sh[];
    const int tid = threadIdx.x;
    for (int i = tid; i < BQ * HH / 4; i += 256)
        ((float4*)sh)[i] = ((const float4*)h)[i];
    __syncthreads();

    const int w = tid >> 5, lane = tid & 31;
#pragma unroll 1
    for (int i = 0; i < 4; ++i) {
        int n = blockIdx.x * 32 + w * 4 + i;
        float acc[16];
#pragma unroll
        for (int b = 0; b < 16; ++b) acc[b] = 0.f;
#pragma unroll
        for (int it = 0; it < 8; ++it) {
            int kq = it * 32 + lane;
            float4 wv = __ldg(((const float4*)(dw + (size_t)n * HH)) + kq);
#pragma unroll
            for (int b = 0; b < 16; ++b) {
                float4 hv = *(((const float4*)(sh + b * HH)) + kq);
                acc[b] += wv.x * hv.x + wv.y * hv.y + wv.z * hv.z + wv.w * hv.w;
            }
        }
        float myv = 0.f;
#pragma unroll
        for (int b = 0; b < 16; ++b) {
            float v = acc[b];
            v += __shfl_xor_sync(0xffffffffu, v, 16);
            v += __shfl_xor_sync(0xffffffffu, v, 8);
            v += __shfl_xor_sync(0xffffffffu, v, 4);
            v += __shfl_xor_sync(0xffffffffu, v, 2);
            v += __shfl_xor_sync(0xffffffffu, v, 1);
            if (lane == b) myv = v;
        }
        if (lane < 16) out[(size_t)lane * NNDIM + n] = myv + __ldg(db + n);
    }
}

// =====================================================================
extern "C" void kernel_launch(void* const* d_in, const int* in_sizes, int n_in,
                              void* d_out, int out_size)
{
    const float* x      = (const float*)d_in[0];
    const float* w_ih0  = (const float*)d_in[1];
    const float* w_hh0  = (const float*)d_in[2];
    const float* b_ih0  = (const float*)d_in[3];
    const float* b_hh0  = (const float*)d_in[4];
    const float* w_ih1  = (const float*)d_in[5];
    const float* w_hh1  = (const float*)d_in[6];
    const float* b_ih1  = (const float*)d_in[7];
    const float* b_hh1  = (const float*)d_in[8];
    const float* dec_w  = (const float*)d_in[9];
    const float* dec_b  = (const float*)d_in[10];
    float* out = (float*)d_out;

    float *gates, *seq, *hbuf;
    cudaGetSymbolAddress((void**)&gates, g_gates);
    cudaGetSymbolAddress((void**)&seq,   g_seq);
    cudaGetSymbolAddress((void**)&hbuf,  g_hbuf);

    cudaFuncSetAttribute(gru_recurrence,
                         cudaFuncAttributeMaxDynamicSharedMemorySize, REC_SMEM);
    cudaFuncSetAttribute(decoder_kernel,
                         cudaFuncAttributeMaxDynamicSharedMemorySize, BQ * HH * 4);

    dim3 gdim(G3 / GBN, (BQ * TT) / GBM);  // (24, 16)

    // layer 0
    gemm_nt_bias<<<gdim, 128>>>(x, w_ih0, b_ih0, gates, BQ * TT, G3, NNDIM);
    gru_recurrence<<<RCTA, 256, REC_SMEM>>>(w_hh0, b_hh0, gates, seq, 1);
    // layer 1
    gemm_nt_bias<<<gdim, 128>>>(seq, w_ih1, b_ih1, gates, BQ * TT, G3, HH);
    gru_recurrence<<<RCTA, 256, REC_SMEM>>>(w_hh1, b_hh1, gates, seq, 0);
    // decoder: final h lives in g_hbuf[0] (T=64 even)
    decoder_kernel<<<NNDIM / 32, 256, BQ * HH * 4>>>(hbuf, dec_w, dec_b, out);
}

// round 2
// speedup vs baseline: 1.0093x; 1.0093x over previous
#include <cuda_runtime.h>
#include <math.h>

#define BQ 16
#define TT 64
#define HH 1024
#define NNDIM 4096
#define G3 3072

typedef unsigned long long u64;

// ---------- packed f32x2 helpers (FFMA2: full-rate fp32 on sm_103a) ----------
__device__ __forceinline__ u64 pk2(float lo, float hi) {
    u64 r; asm("mov.b64 %0,{%1,%2};" : "=l"(r) : "f"(lo), "f"(hi)); return r;
}
__device__ __forceinline__ float2 upk2(u64 v) {
    float2 f; asm("mov.b64 {%0,%1},%2;" : "=f"(f.x), "=f"(f.y) : "l"(v)); return f;
}
__device__ __forceinline__ void fma2(u64 &d, u64 a, u64 b) {
    asm("fma.rn.f32x2 %0,%1,%2,%0;" : "+l"(d) : "l"(a), "l"(b));
}

// ---------- device scratch (no allocations allowed) ----------
__device__ float g_gates[BQ * TT * G3];   // 12.6 MB, reused by both layers
__device__ float g_seq[BQ * TT * HH];     // 4 MB, layer-0 output sequence
__device__ float g_hbuf[2][BQ * HH];      // ping-pong hidden state
__device__ unsigned g_count = 0;
__device__ volatile unsigned g_gen = 0;

// =====================================================================
// GEMM: C[M,N] = A[M,K] @ Bw[N,K]^T + bias[N]   (all row-major, f32)
// BM=64, BN=128, BK=16, 128 threads, 8x8 microtile, f32x2 FMAs,
// register-prefetch pipeline: next k-tile's global loads are issued
// before computing the current smem tile, hiding DRAM/L2 latency.
// =====================================================================
#define GBM 64
#define GBN 128
#define GBK 16

__global__ void __launch_bounds__(128, 2) gemm_nt_bias(
    const float* __restrict__ A, const float* __restrict__ Bw,
    const float* __restrict__ bias, float* __restrict__ C,
    int M, int N, int K)
{
    __shared__ __align__(16) float As[GBK][GBM + 4];
    __shared__ __align__(16) float Bs[GBK][GBN + 4];

    const int tid = threadIdx.x;
    const int tn = tid & 15;        // 0..15  -> 8 cols each
    const int tm = tid >> 4;        // 0..7   -> 8 rows each
    const int m0 = blockIdx.y * GBM;
    const int n0 = blockIdx.x * GBN;

    // per-thread load coordinates
    const int rA0 = tid >> 2;            // A rows: tid/4 and tid/4+32
    const int c4  = (tid & 3) * 4;       // k offset within tile
    const float* pA0 = A  + (size_t)(m0 + rA0)      * K + c4;
    const float* pA1 = A  + (size_t)(m0 + rA0 + 32) * K + c4;
    const float* pB0 = Bw + (size_t)(n0 + rA0)      * K + c4;
    const float* pB1 = Bw + (size_t)(n0 + rA0 + 32) * K + c4;
    const float* pB2 = Bw + (size_t)(n0 + rA0 + 64) * K + c4;
    const float* pB3 = Bw + (size_t)(n0 + rA0 + 96) * K + c4;

    u64 acc[8][4];
#pragma unroll
    for (int i = 0; i < 8; ++i)
#pragma unroll
        for (int j = 0; j < 4; ++j) acc[i][j] = 0ull;

    // preload tile 0 into registers
    float4 ra0 = *(const float4*)pA0;
    float4 ra1 = *(const float4*)pA1;
    float4 rb0 = *(const float4*)pB0;
    float4 rb1 = *(const float4*)pB1;
    float4 rb2 = *(const float4*)pB2;
    float4 rb3 = *(const float4*)pB3;

    for (int k0 = 0; k0 < K; k0 += GBK) {
        // store staged registers into smem (transposed)
        As[c4 + 0][rA0]      = ra0.x; As[c4 + 1][rA0]      = ra0.y;
        As[c4 + 2][rA0]      = ra0.z; As[c4 + 3][rA0]      = ra0.w;
        As[c4 + 0][rA0 + 32] = ra1.x; As[c4 + 1][rA0 + 32] = ra1.y;
        As[c4 + 2][rA0 + 32] = ra1.z; As[c4 + 3][rA0 + 32] = ra1.w;
        Bs[c4 + 0][rA0]      = rb0.x; Bs[c4 + 1][rA0]      = rb0.y;
        Bs[c4 + 2][rA0]      = rb0.z; Bs[c4 + 3][rA0]      = rb0.w;
        Bs[c4 + 0][rA0 + 32] = rb1.x; Bs[c4 + 1][rA0 + 32] = rb1.y;
        Bs[c4 + 2][rA0 + 32] = rb1.z; Bs[c4 + 3][rA0 + 32] = rb1.w;
        Bs[c4 + 0][rA0 + 64] = rb2.x; Bs[c4 + 1][rA0 + 64] = rb2.y;
        Bs[c4 + 2][rA0 + 64] = rb2.z; Bs[c4 + 3][rA0 + 64] = rb2.w;
        Bs[c4 + 0][rA0 + 96] = rb3.x; Bs[c4 + 1][rA0 + 96] = rb3.y;
        Bs[c4 + 2][rA0 + 96] = rb3.z; Bs[c4 + 3][rA0 + 96] = rb3.w;
        __syncthreads();

        // prefetch next tile into registers (overlaps compute below)
        if (k0 + GBK < K) {
            pA0 += GBK; pA1 += GBK; pB0 += GBK; pB1 += GBK; pB2 += GBK; pB3 += GBK;
            ra0 = *(const float4*)pA0;
            ra1 = *(const float4*)pA1;
            rb0 = *(const float4*)pB0;
            rb1 = *(const float4*)pB1;
            rb2 = *(const float4*)pB2;
            rb3 = *(const float4*)pB3;
        }

#pragma unroll
        for (int kk = 0; kk < GBK; ++kk) {
            float4 aA = *(const float4*)&As[kk][tm * 8];
            float4 aB = *(const float4*)&As[kk][tm * 8 + 4];
            u64 av[8] = { pk2(aA.x, aA.x), pk2(aA.y, aA.y), pk2(aA.z, aA.z), pk2(aA.w, aA.w),
                          pk2(aB.x, aB.x), pk2(aB.y, aB.y), pk2(aB.z, aB.z), pk2(aB.w, aB.w) };
            ulonglong2 bA = *(const ulonglong2*)&Bs[kk][tn * 8];
            ulonglong2 bB = *(const ulonglong2*)&Bs[kk][tn * 8 + 4];
            u64 bv[4] = { bA.x, bA.y, bB.x, bB.y };
#pragma unroll
            for (int i = 0; i < 8; ++i)
#pragma unroll
                for (int j = 0; j < 4; ++j) fma2(acc[i][j], av[i], bv[j]);
        }
        __syncthreads();
    }

#pragma unroll
    for (int i = 0; i < 8; ++i) {
        int m = m0 + tm * 8 + i;
#pragma unroll
        for (int j = 0; j < 4; ++j) {
            int n = n0 + tn * 8 + j * 2;
            float2 v = upk2(acc[i][j]);
            float2 o;
            o.x = v.x + __ldg(bias + n);
            o.y = v.y + __ldg(bias + n + 1);
            *(float2*)(C + (size_t)m * N + n) = o;
        }
    }
}

// =====================================================================
// Persistent GRU recurrence. 128 CTAs x 256 threads, all co-resident
// (165 KB dyn smem -> 1 CTA/SM). w_hh slice lives in SMEM across all
// 64 steps; h broadcast via L2 with a software grid barrier per step.
// =====================================================================
#define RCTA 128
#define REC_SMEM ((24 * HH + 16 * HH + 8 * 48) * 4)

__device__ __forceinline__ void grid_barrier_dev() {
    __syncthreads();
    if (threadIdx.x == 0) {
        __threadfence();                       // publish my CTA's stores
        unsigned gen = g_gen;
        if (atomicAdd(&g_count, 1u) == (unsigned)(gridDim.x - 1)) {
            g_count = 0;
            __threadfence();
            g_gen = gen + 1;
        } else {
            while (g_gen == gen) { }
        }
        __threadfence();                       // gpu-scope fence: invalidates L1 (B300)
    }
    __syncthreads();
}

__global__ void __launch_bounds__(256, 1) gru_recurrence(
    const float* __restrict__ w_hh, const float* __restrict__ b_hh,
    const float* __restrict__ gates, float* __restrict__ seq_out,
    int write_seq)
{
    extern __shared__ __align__(16) float smem[];
    float* sW   = smem;               // [24][1024]  rows: unit-local*3 + gate
    float* sH   = smem + 24 * HH;     // [16][1024]
    float* sRed = smem + 40 * HH;     // [8][48] per-warp reduction scratch

    const int tid  = threadIdx.x;
    const int w    = tid >> 5;
    const int lane = tid & 31;
    const int ubase = blockIdx.x * 8;
    const int up = w & 3;             // unit-pair index (units up*2, up*2+1)
    const int bh = w >> 2;            // batch half (8 batches)
    const int rbase = up * 6;

    // ---- load w_hh slice to SMEM (stays for all 64 steps) ----
    for (int i = tid; i < 24 * HH / 4; i += 256) {
        int row = i >> 8;             // 0..23
        int c   = (i & 255) * 4;
        int lu  = row / 3;
        int g   = row - lu * 3;
        *(float4*)&sW[row * HH + c] =
            *(const float4*)&w_hh[(size_t)(g * HH + ubase + lu) * HH + c];
    }

    // ---- zero h0 (buffer 0) across the grid ----
    {
        int idx = blockIdx.x * 256 + tid;
        if (idx < BQ * HH) g_hbuf[0][idx] = 0.f;
    }

    // ---- per-lane epilogue constants ----
    const int ul   = (lane >> 3) & 1;
    const int bl   = lane & 7;
    const int b_ep = bh * 8 + bl;
    const int u_ep = ubase + up * 2 + ul;
    float bhr = 0.f, bhz = 0.f, bhn = 0.f;
    if (lane < 16) {
        bhr = b_hh[u_ep];
        bhz = b_hh[HH + u_ep];
        bhn = b_hh[2 * HH + u_ep];
    }

    grid_barrier_dev();   // zeros + weights visible everywhere

    for (int t = 0; t < TT; ++t) {
        const float* hsrc = g_hbuf[t & 1];
        float* hdst = g_hbuf[(t + 1) & 1];

        // prefetch this step's gates_x for the epilogue (long slack)
        float gxr = 0.f, gxz = 0.f, gxn = 0.f;
        if (lane < 16) {
            const float* gp = gates + (size_t)(b_ep * TT + t) * G3 + u_ep;
            gxr = __ldg(gp);
            gxz = __ldg(gp + HH);
            gxn = __ldg(gp + 2 * HH);
        }

        // stage h (L2-only loads: other CTAs wrote it last step)
        for (int i = tid; i < BQ * HH / 4; i += 256) {
            float4 v = __ldcg(((const float4*)hsrc) + i);
            *(((float4*)sH) + i) = v;
        }
        __syncthreads();

        // ---- main accumulation: 6 rows x 8 batches, k=1024 ----
        u64 acc[6][8];
#pragma unroll
        for (int r = 0; r < 6; ++r)
#pragma unroll
            for (int b = 0; b < 8; ++b) acc[r][b] = 0ull;

#pragma unroll
        for (int it = 0; it < 8; ++it) {
            int kq = it * 32 + lane;  // 16B-unit index (256 per 1024-float row)
            ulonglong2 hv[8];
#pragma unroll
            for (int b = 0; b < 8; ++b)
                hv[b] = *(((const ulonglong2*)(sH + (bh * 8 + b) * HH)) + kq);
#pragma unroll
            for (int r = 0; r < 6; ++r) {
                ulonglong2 wv = *(((const ulonglong2*)(sW + (rbase + r) * HH)) + kq);
#pragma unroll
                for (int b = 0; b < 8; ++b) {
                    fma2(acc[r][b], wv.x, hv[b].x);
                    fma2(acc[r][b], wv.y, hv[b].y);
                }
            }
        }

        // ---- warp reduction -> smem scratch ----
#pragma unroll
        for (int r = 0; r < 6; ++r) {
#pragma unroll
            for (int b = 0; b < 8; ++b) {
                float2 f = upk2(acc[r][b]);
                float v = f.x + f.y;
                v += __shfl_xor_sync(0xffffffffu, v, 16);
                v += __shfl_xor_sync(0xffffffffu, v, 8);
                v += __shfl_xor_sync(0xffffffffu, v, 4);
                v += __shfl_xor_sync(0xffffffffu, v, 2);
                v += __shfl_xor_sync(0xffffffffu, v, 1);
                if (lane == 0) sRed[w * 48 + r * 8 + b] = v;
            }
        }
        __syncwarp();

        // ---- GRU gate epilogue (16 lanes = 2 units x 8 batches) ----
        if (lane < 16) {
            float ghr = sRed[w * 48 + (ul * 3 + 0) * 8 + bl] + bhr;
            float ghz = sRed[w * 48 + (ul * 3 + 1) * 8 + bl] + bhz;
            float ghn = sRed[w * 48 + (ul * 3 + 2) * 8 + bl] + bhn;
            float rr = 1.f / (1.f + __expf(-(gxr + ghr)));
            float zz = 1.f / (1.f + __expf(-(gxz + ghz)));
            float nn = tanhf(gxn + rr * ghn);
            float hp = sH[b_ep * HH + u_ep];
            float hv = (1.f - zz) * nn + zz * hp;
            __stcg(&hdst[b_ep * HH + u_ep], hv);
            if (write_seq)
                seq_out[(size_t)(b_ep * TT + t) * HH + u_ep] = hv;
        }

        if (t + 1 < TT) grid_barrier_dev();   // kernel boundary covers the last step
    }
}

// =====================================================================
// Decoder: out[b,n] = h[b,:] . dec_w[n,:] + dec_b[n]   (M=16,N=4096,K=1024)
// =====================================================================
__global__ void __launch_bounds__(256) decoder_kernel(
    const float* __restrict__ h, const float* __restrict__ dw,
    const float* __restrict__ db, float* __restrict__ out)
{
    extern __shared__ __align__(16) float sh[];
    const int tid = threadIdx.x;
    for (int i = tid; i < BQ * HH / 4; i += 256)
        ((float4*)sh)[i] = ((const float4*)h)[i];
    __syncthreads();

    const int w = tid >> 5, lane = tid & 31;
#pragma unroll 1
    for (int i = 0; i < 4; ++i) {
        int n = blockIdx.x * 32 + w * 4 + i;
        float acc[16];
#pragma unroll
        for (int b = 0; b < 16; ++b) acc[b] = 0.f;
#pragma unroll
        for (int it = 0; it < 8; ++it) {
            int kq = it * 32 + lane;
            float4 wv = __ldg(((const float4*)(dw + (size_t)n * HH)) + kq);
#pragma unroll
            for (int b = 0; b < 16; ++b) {
                float4 hv = *(((const float4*)(sh + b * HH)) + kq);
                acc[b] += wv.x * hv.x + wv.y * hv.y + wv.z * hv.z + wv.w * hv.w;
            }
        }
        float myv = 0.f;
#pragma unroll
        for (int b = 0; b < 16; ++b) {
            float v = acc[b];
            v += __shfl_xor_sync(0xffffffffu, v, 16);
            v += __shfl_xor_sync(0xffffffffu, v, 8);
            v += __shfl_xor_sync(0xffffffffu, v, 4);
            v += __shfl_xor_sync(0xffffffffu, v, 2);
            v += __shfl_xor_sync(0xffffffffu, v, 1);
            if (lane == b) myv = v;
        }
        if (lane < 16) out[(size_t)lane * NNDIM + n] = myv + __ldg(db + n);
    }
}

// =====================================================================
extern "C" void kernel_launch(void* const* d_in, const int* in_sizes, int n_in,
                              void* d_out, int out_size)
{
    const float* x      = (const float*)d_in[0];
    const float* w_ih0  = (const float*)d_in[1];
    const float* w_hh0  = (const float*)d_in[2];
    const float* b_ih0  = (const float*)d_in[3];
    const float* b_hh0  = (const float*)d_in[4];
    const float* w_ih1  = (const float*)d_in[5];
    const float* w_hh1  = (const float*)d_in[6];
    const float* b_ih1  = (const float*)d_in[7];
    const float* b_hh1  = (const float*)d_in[8];
    const float* dec_w  = (const float*)d_in[9];
    const float* dec_b  = (const float*)d_in[10];
    float* out = (float*)d_out;

    float *gates, *seq, *hbuf;
    cudaGetSymbolAddress((void**)&gates, g_gates);
    cudaGetSymbolAddress((void**)&seq,   g_seq);
    cudaGetSymbolAddress((void**)&hbuf,  g_hbuf);

    cudaFuncSetAttribute(gru_recurrence,
                         cudaFuncAttributeMaxDynamicSharedMemorySize, REC_SMEM);
    cudaFuncSetAttribute(decoder_kernel,
                         cudaFuncAttributeMaxDynamicSharedMemorySize, BQ * HH * 4);

    dim3 gdim(G3 / GBN, (BQ * TT) / GBM);  // (24, 16)

    // layer 0
    gemm_nt_bias<<<gdim, 128>>>(x, w_ih0, b_ih0, gates, BQ * TT, G3, NNDIM);
    gru_recurrence<<<RCTA, 256, REC_SMEM>>>(w_hh0, b_hh0, gates, seq, 1);
    // layer 1
    gemm_nt_bias<<<gdim, 128>>>(seq, w_ih1, b_ih1, gates, BQ * TT, G3, HH);
    gru_recurrence<<<RCTA, 256, REC_SMEM>>>(w_hh1, b_hh1, gates, seq, 0);
    // decoder: final h lives in g_hbuf[0] (T=64 even)
    decoder_kernel<<<NNDIM / 32, 256, BQ * HH * 4>>>(hbuf, dec_w, dec_b, out);
}

// round 4
// speedup vs baseline: 1.1785x; 1.1676x over previous
#include <cuda_runtime.h>
#include <cuda_bf16.h>
#include <math.h>

#define BQ 16
#define TT 64
#define HH 1024
#define NNDIM 4096
#define G3 3072

typedef unsigned long long u64;
typedef unsigned int u32;

// ---------- packed f32x2 helpers ----------
__device__ __forceinline__ u64 pk2(float lo, float hi) {
    u64 r; asm("mov.b64 %0,{%1,%2};" : "=l"(r) : "f"(lo), "f"(hi)); return r;
}
__device__ __forceinline__ float2 upk2(u64 v) {
    float2 f; asm("mov.b64 {%0,%1},%2;" : "=f"(f.x), "=f"(f.y) : "l"(v)); return f;
}
__device__ __forceinline__ void fma2(u64 &d, u64 a, u64 b) {
    asm("fma.rn.f32x2 %0,%1,%2,%0;" : "+l"(d) : "l"(a), "l"(b));
}

// ---------- device scratch ----------
__device__ float g_gates[BQ * TT * G3];
__device__ float g_seq[BQ * TT * HH];
__device__ float g_hbuf[2][BQ * HH];
__device__ unsigned g_count = 0;
__device__ volatile unsigned g_gen = 0;
// split-bf16 row-major matrices (K -> 3K packing)
__device__ unsigned short g_wcvt[(size_t)G3 * 3 * NNDIM];       // 75.5 MB max
__device__ unsigned short g_acvt[(size_t)BQ * TT * 3 * NNDIM];  // 25.2 MB max

__device__ __forceinline__ u32 smem_u32(const void* p) {
    u32 a; asm("{ .reg .u64 t; cvta.to.shared.u64 t, %1; cvt.u32.u64 %0, t; }" : "=r"(a) : "l"(p));
    return a;
}
__device__ __forceinline__ void cp_async16(u32 dst, const void* src) {
    asm volatile("cp.async.cg.shared.global [%0], [%1], 16;" :: "r"(dst), "l"(src) : "memory");
}
__device__ __forceinline__ void cp_commit() {
    asm volatile("cp.async.commit_group;" ::: "memory");
}
__device__ __forceinline__ void cp_wait1() {
    asm volatile("cp.async.wait_group 1;" ::: "memory");
}
__device__ __forceinline__ void ldsm_x4(u32* r, u32 addr) {
    asm volatile("ldmatrix.sync.aligned.m8n8.x4.shared.b16 {%0,%1,%2,%3}, [%4];"
                 : "=r"(r[0]), "=r"(r[1]), "=r"(r[2]), "=r"(r[3]) : "r"(addr));
}
__device__ __forceinline__ void mma16816(float* c, const u32* a, const u32* b) {
    asm volatile(
        "mma.sync.aligned.m16n8k16.row.col.f32.bf16.bf16.f32 "
        "{%0,%1,%2,%3}, {%4,%5,%6,%7}, {%8,%9}, {%0,%1,%2,%3};"
        : "+f"(c[0]), "+f"(c[1]), "+f"(c[2]), "+f"(c[3])
        : "r"(a[0]), "r"(a[1]), "r"(a[2]), "r"(a[3]), "r"(b[0]), "r"(b[1]));
}

// =====================================================================
// conv_split_rm: fp32 [rows, K] -> split-bf16 row-major [rows, 3K]
// columns 3k+v: a_mode=1 (A): v0=hi,v1=lo,v2=hi ; a_mode=0 (W): v0=hi,v1=hi,v2=lo
// thread handles 8 k -> 24 bf16 = 3 x 16B stores (aligned).
// =====================================================================
__global__ void conv_split_rm(const float* __restrict__ src, unsigned short* __restrict__ dst,
                              int K, int total, int a_mode)
{
    int t = blockIdx.x * blockDim.x + threadIdx.x;
    if (t >= total) return;
    int kg = t % (K >> 3);
    int r  = t / (K >> 3);
    const float4* p = (const float4*)(src + (size_t)r * K + kg * 8);
    float v[8];
    float4 f0 = __ldg(p), f1 = __ldg(p + 1);
    v[0]=f0.x; v[1]=f0.y; v[2]=f0.z; v[3]=f0.w;
    v[4]=f1.x; v[5]=f1.y; v[6]=f1.z; v[7]=f1.w;
    unsigned short o[24];
#pragma unroll
    for (int k = 0; k < 8; ++k) {
        __nv_bfloat16 hi = __float2bfloat16(v[k]);
        __nv_bfloat16 lo = __float2bfloat16(v[k] - __bfloat162float(hi));
        unsigned short hs = *(unsigned short*)&hi;
        unsigned short ls = *(unsigned short*)&lo;
        o[3*k+0] = hs;
        o[3*k+1] = a_mode ? ls : hs;
        o[3*k+2] = a_mode ? hs : ls;
    }
    unsigned short* d = dst + (size_t)r * 3 * K + (size_t)kg * 24;
    ((uint4*)d)[0] = ((uint4*)o)[0];
    ((uint4*)d)[1] = ((uint4*)o)[1];
    ((uint4*)d)[2] = ((uint4*)o)[2];
}

// =====================================================================
// bf16 tensor-core GEMM: C[M,N] = A[M,Keff] @ W[N,Keff]^T + bias
// CTA 128x128, 8 warps (warp tile 64x32), k-chunk 32, 3-stage cp.async,
// xor-swizzled smem + ldmatrix.x4 + mma.m16n8k16.
// =====================================================================
__global__ void __launch_bounds__(256, 1) gemm_bf16_tc(
    const unsigned short* __restrict__ A, const unsigned short* __restrict__ W,
    const float* __restrict__ bias, float* __restrict__ C, int Keff)
{
    __shared__ __align__(1024) char buf[3][16384];   // per stage: A 8KB + B 8KB

    const int tid  = threadIdx.x;
    const int wid  = tid >> 5;
    const int lane = tid & 31;
    const int warp_m = wid & 1;       // 0..1 -> 64 rows
    const int warp_n = wid >> 1;      // 0..3 -> 32 cols
    const int m0 = blockIdx.y * 128;
    const int n0 = blockIdx.x * 128;
    const u32 sbase = smem_u32(buf);
    const size_t strideB = (size_t)Keff * 2;   // bytes per row
    const int niter = Keff / 32;

    float c[4][4][4];
#pragma unroll
    for (int i = 0; i < 4; ++i)
#pragma unroll
        for (int j = 0; j < 4; ++j)
#pragma unroll
            for (int q = 0; q < 4; ++q) c[i][j][q] = 0.f;

    // per-thread load coords (2 units A + 2 units B per stage)
    const int rowL = tid >> 2;          // 0..63 (tid) and +64
    const int uL   = tid & 3;

    // ---- prologue: stages 0,1 ----
#pragma unroll
    for (int s = 0; s < 2; ++s) {
        u32 ab = sbase + s * 16384;
#pragma unroll
        for (int q = 0; q < 2; ++q) {
            int row = rowL + q * 64;
            int p = uL ^ ((row >> 1) & 3);
            cp_async16(ab + row * 64 + p * 16,
                       (const char*)A + (size_t)(m0 + row) * strideB + (size_t)s * 64 + uL * 16);
            cp_async16(ab + 8192 + row * 64 + p * 16,
                       (const char*)W + (size_t)(n0 + row) * strideB + (size_t)s * 64 + uL * 16);
        }
        cp_commit();
    }

    for (int i = 0; i < niter; ++i) {
        cp_wait1();
        __syncthreads();

        // issue loads for stage i+2
        if (i + 2 < niter) {
            u32 ab = sbase + ((i + 2) % 3) * 16384;
#pragma unroll
            for (int q = 0; q < 2; ++q) {
                int row = rowL + q * 64;
                int p = uL ^ ((row >> 1) & 3);
                cp_async16(ab + row * 64 + p * 16,
                           (const char*)A + (size_t)(m0 + row) * strideB + (size_t)(i + 2) * 64 + uL * 16);
                cp_async16(ab + 8192 + row * 64 + p * 16,
                           (const char*)W + (size_t)(n0 + row) * strideB + (size_t)(i + 2) * 64 + uL * 16);
            }
        }
        cp_commit();

        // compute from stage i%3
        u32 abase = sbase + (i % 3) * 16384;
        u32 bbase = abase + 8192;
        const int mi = lane >> 3;
        const int rl = lane & 7;
#pragma unroll
        for (int h = 0; h < 2; ++h) {
            u32 afr[4][4];
#pragma unroll
            for (int mt = 0; mt < 4; ++mt) {
                int row = warp_m * 64 + mt * 16 + (mi & 1) * 8 + rl;
                int u = 2 * h + (mi >> 1);
                int p = u ^ ((row >> 1) & 3);
                ldsm_x4(afr[mt], abase + row * 64 + p * 16);
            }
            u32 bfr[4][2];
#pragma unroll
            for (int pp = 0; pp < 2; ++pp) {
                int j = pp * 2 + (mi >> 1);
                int row = warp_n * 32 + j * 8 + rl;
                int u = 2 * h + (mi & 1);
                int p = u ^ ((row >> 1) & 3);
                u32 r4[4];
                ldsm_x4(r4, bbase + row * 64 + p * 16);
                bfr[pp*2][0] = r4[0]; bfr[pp*2][1] = r4[1];
                bfr[pp*2+1][0] = r4[2]; bfr[pp*2+1][1] = r4[3];
            }
#pragma unroll
            for (int mt = 0; mt < 4; ++mt)
#pragma unroll
                for (int nt = 0; nt < 4; ++nt)
                    mma16816(c[mt][nt], afr[mt], bfr[nt]);
        }
        __syncthreads();
    }

    // ---- epilogue ----
    const int mwb = m0 + warp_m * 64;
    const int nwb = n0 + warp_n * 32;
#pragma unroll
    for (int mt = 0; mt < 4; ++mt) {
#pragma unroll
        for (int nt = 0; nt < 4; ++nt) {
            int m = mwb + mt * 16 + (lane >> 2);
            int n = nwb + nt * 8 + (lane & 3) * 2;
            float bx = __ldg(bias + n), by = __ldg(bias + n + 1);
            float2 o0 = { c[mt][nt][0] + bx, c[mt][nt][1] + by };
            float2 o1 = { c[mt][nt][2] + bx, c[mt][nt][3] + by };
            *(float2*)(C + (size_t)m * G3 + n) = o0;
            *(float2*)(C + (size_t)(m + 8) * G3 + n) = o1;
        }
    }
}

// =====================================================================
// Persistent GRU recurrence (unchanged, passing)
// =====================================================================
#define RCTA 128
#define REC_SMEM ((24 * HH + 16 * HH + 8 * 48) * 4)

__device__ __forceinline__ void grid_barrier_dev() {
    __syncthreads();
    if (threadIdx.x == 0) {
        __threadfence();
        unsigned gen = g_gen;
        if (atomicAdd(&g_count, 1u) == (unsigned)(gridDim.x - 1)) {
            g_count = 0;
            __threadfence();
            g_gen = gen + 1;
        } else {
            while (g_gen == gen) { }
        }
        __threadfence();
    }
    __syncthreads();
}

__global__ void __launch_bounds__(256, 1) gru_recurrence(
    const float* __restrict__ w_hh, const float* __restrict__ b_hh,
    const float* __restrict__ gates, float* __restrict__ seq_out,
    int write_seq)
{
    extern __shared__ __align__(16) float smemf[];
    float* sW   = smemf;
    float* sH   = smemf + 24 * HH;
    float* sRed = smemf + 40 * HH;

    const int tid  = threadIdx.x;
    const int w    = tid >> 5;
    const int lane = tid & 31;
    const int ubase = blockIdx.x * 8;
    const int up = w & 3;
    const int bh = w >> 2;
    const int rbase = up * 6;

    for (int i = tid; i < 24 * HH / 4; i += 256) {
        int row = i >> 8;
        int c   = (i & 255) * 4;
        int lu  = row / 3;
        int g   = row - lu * 3;
        *(float4*)&sW[row * HH + c] =
            *(const float4*)&w_hh[(size_t)(g * HH + ubase + lu) * HH + c];
    }
    {
        int idx = blockIdx.x * 256 + tid;
        if (idx < BQ * HH) g_hbuf[0][idx] = 0.f;
    }

    const int ul   = (lane >> 3) & 1;
    const int bl   = lane & 7;
    const int b_ep = bh * 8 + bl;
    const int u_ep = ubase + up * 2 + ul;
    float bhr = 0.f, bhz = 0.f, bhn = 0.f;
    if (lane < 16) {
        bhr = b_hh[u_ep];
        bhz = b_hh[HH + u_ep];
        bhn = b_hh[2 * HH + u_ep];
    }

    grid_barrier_dev();

    for (int t = 0; t < TT; ++t) {
        const float* hsrc = g_hbuf[t & 1];
        float* hdst = g_hbuf[(t + 1) & 1];

        float gxr = 0.f, gxz = 0.f, gxn = 0.f;
        if (lane < 16) {
            const float* gp = gates + (size_t)(b_ep * TT + t) * G3 + u_ep;
            gxr = __ldg(gp);
            gxz = __ldg(gp + HH);
            gxn = __ldg(gp + 2 * HH);
        }

        for (int i = tid; i < BQ * HH / 4; i += 256) {
            float4 v = __ldcg(((const float4*)hsrc) + i);
            *(((float4*)sH) + i) = v;
        }
        __syncthreads();

        u64 acc[6][8];
#pragma unroll
        for (int r = 0; r < 6; ++r)
#pragma unroll
            for (int b = 0; b < 8; ++b) acc[r][b] = 0ull;

#pragma unroll
        for (int it = 0; it < 8; ++it) {
            int kq = it * 32 + lane;
            ulonglong2 hv[8];
#pragma unroll
            for (int b = 0; b < 8; ++b)
                hv[b] = *(((const ulonglong2*)(sH + (bh * 8 + b) * HH)) + kq);
#pragma unroll
            for (int r = 0; r < 6; ++r) {
                ulonglong2 wv = *(((const ulonglong2*)(sW + (rbase + r) * HH)) + kq);
#pragma unroll
                for (int b = 0; b < 8; ++b) {
                    fma2(acc[r][b], wv.x, hv[b].x);
                    fma2(acc[r][b], wv.y, hv[b].y);
                }
            }
        }

#pragma unroll
        for (int r = 0; r < 6; ++r) {
#pragma unroll
            for (int b = 0; b < 8; ++b) {
                float2 f = upk2(acc[r][b]);
                float v = f.x + f.y;
                v += __shfl_xor_sync(0xffffffffu, v, 16);
                v += __shfl_xor_sync(0xffffffffu, v, 8);
                v += __shfl_xor_sync(0xffffffffu, v, 4);
                v += __shfl_xor_sync(0xffffffffu, v, 2);
                v += __shfl_xor_sync(0xffffffffu, v, 1);
                if (lane == 0) sRed[w * 48 + r * 8 + b] = v;
            }
        }
        __syncwarp();

        if (lane < 16) {
            float ghr = sRed[w * 48 + (ul * 3 + 0) * 8 + bl] + bhr;
            float ghz = sRed[w * 48 + (ul * 3 + 1) * 8 + bl] + bhz;
            float ghn = sRed[w * 48 + (ul * 3 + 2) * 8 + bl] + bhn;
            float rr = 1.f / (1.f + __expf(-(gxr + ghr)));
            float zz = 1.f / (1.f + __expf(-(gxz + ghz)));
            float nn = tanhf(gxn + rr * ghn);
            float hp = sH[b_ep * HH + u_ep];
            float hv = (1.f - zz) * nn + zz * hp;
            __stcg(&hdst[b_ep * HH + u_ep], hv);
            if (write_seq)
                seq_out[(size_t)(b_ep * TT + t) * HH + u_ep] = hv;
        }

        if (t + 1 < TT) grid_barrier_dev();
    }
}

// =====================================================================
// Decoder (unchanged)
// =====================================================================
__global__ void __launch_bounds__(256) decoder_kernel(
    const float* __restrict__ h, const float* __restrict__ dw,
    const float* __restrict__ db, float* __restrict__ out)
{
    extern __shared__ __align__(16) float sh[];
    const int tid = threadIdx.x;
    for (int i = tid; i < BQ * HH / 4; i += 256)
        ((float4*)sh)[i] = ((const float4*)h)[i];
    __syncthreads();

    const int w = tid >> 5, lane = tid & 31;
#pragma unroll 1
    for (int i = 0; i < 4; ++i) {
        int n = blockIdx.x * 32 + w * 4 + i;
        float acc[16];
#pragma unroll
        for (int b = 0; b < 16; ++b) acc[b] = 0.f;
#pragma unroll
        for (int it = 0; it < 8; ++it) {
            int kq = it * 32 + lane;
            float4 wv = __ldg(((const float4*)(dw + (size_t)n * HH)) + kq);
#pragma unroll
            for (int b = 0; b < 16; ++b) {
                float4 hv = *(((const float4*)(sh + b * HH)) + kq);
                acc[b] += wv.x * hv.x + wv.y * hv.y + wv.z * hv.z + wv.w * hv.w;
            }
        }
        float myv = 0.f;
#pragma unroll
        for (int b = 0; b < 16; ++b) {
            float v = acc[b];
            v += __shfl_xor_sync(0xffffffffu, v, 16);
            v += __shfl_xor_sync(0xffffffffu, v, 8);
            v += __shfl_xor_sync(0xffffffffu, v, 4);
            v += __shfl_xor_sync(0xffffffffu, v, 2);
            v += __shfl_xor_sync(0xffffffffu, v, 1);
            if (lane == b) myv = v;
        }
        if (lane < 16) out[(size_t)lane * NNDIM + n] = myv + __ldg(db + n);
    }
}

// =====================================================================
extern "C" void kernel_launch(void* const* d_in, const int* in_sizes, int n_in,
                              void* d_out, int out_size)
{
    const float* x      = (const float*)d_in[0];
    const float* w_ih0  = (const float*)d_in[1];
    const float* w_hh0  = (const float*)d_in[2];
    const float* b_ih0  = (const float*)d_in[3];
    const float* b_hh0  = (const float*)d_in[4];
    const float* w_ih1  = (const float*)d_in[5];
    const float* w_hh1  = (const float*)d_in[6];
    const float* b_ih1  = (const float*)d_in[7];
    const float* b_hh1  = (const float*)d_in[8];
    const float* dec_w  = (const float*)d_in[9];
    const float* dec_b  = (const float*)d_in[10];
    float* out = (float*)d_out;

    float *gates, *seq, *hbuf;
    unsigned short *wcvt, *acvt;
    cudaGetSymbolAddress((void**)&gates, g_gates);
    cudaGetSymbolAddress((void**)&seq,   g_seq);
    cudaGetSymbolAddress((void**)&hbuf,  g_hbuf);
    cudaGetSymbolAddress((void**)&wcvt,  g_wcvt);
    cudaGetSymbolAddress((void**)&acvt,  g_acvt);

    cudaFuncSetAttribute(gru_recurrence,
                         cudaFuncAttributeMaxDynamicSharedMemorySize, REC_SMEM);
    cudaFuncSetAttribute(decoder_kernel,
                         cudaFuncAttributeMaxDynamicSharedMemorySize, BQ * HH * 4);

    dim3 ggrid(G3 / 128, (BQ * TT) / 128);   // (24, 8)

    // ---- layer 0 ----
    {
        int K = NNDIM;
        int totW = G3 * (K / 8), totA = BQ * TT * (K / 8);
        conv_split_rm<<<(totW + 255) / 256, 256>>>(w_ih0, wcvt, K, totW, 0);
        conv_split_rm<<<(totA + 255) / 256, 256>>>(x,     acvt, K, totA, 1);
        gemm_bf16_tc<<<ggrid, 256>>>(acvt, wcvt, b_ih0, gates, 3 * K);
    }
    gru_recurrence<<<RCTA, 256, REC_SMEM>>>(w_hh0, b_hh0, gates, seq, 1);

    // ---- layer 1 ----
    {
        int K = HH;
        int totW = G3 * (K / 8), totA = BQ * TT * (K / 8);
        conv_split_rm<<<(totW + 255) / 256, 256>>>(w_ih1, wcvt, K, totW, 0);
        conv_split_rm<<<(totA + 255) / 256, 256>>>(seq,   acvt, K, totA, 1);
        gemm_bf16_tc<<<ggrid, 256>>>(acvt, wcvt, b_ih1, gates, 3 * K);
    }
    gru_recurrence<<<RCTA, 256, REC_SMEM>>>(w_hh1, b_hh1, gates, seq, 0);

    // ---- decoder ----
    decoder_kernel<<<NNDIM / 32, 256, BQ * HH * 4>>>(hbuf, dec_w, dec_b, out);
}

// round 5
// speedup vs baseline: 1.2877x; 1.0927x over previous
#include <cuda_runtime.h>
#include <cuda_bf16.h>
#include <math.h>

#define BQ 16
#define TT 64
#define HH 1024
#define NNDIM 4096
#define G3 3072

typedef unsigned long long u64;
typedef unsigned int u32;

// ---------- device scratch ----------
__device__ float g_gates[BQ * TT * G3];
__device__ float g_seq[BQ * TT * HH];
__device__ float g_hbuf[2][BQ * HH];
__device__ unsigned g_count = 0;
__device__ volatile unsigned g_gen = 0;
__device__ unsigned short g_wcvt[(size_t)G3 * 3 * NNDIM];
__device__ unsigned short g_acvt[(size_t)BQ * TT * 3 * NNDIM];

__device__ __forceinline__ u32 smem_u32(const void* p) {
    u32 a; asm("{ .reg .u64 t; cvta.to.shared.u64 t, %1; cvt.u32.u64 %0, t; }" : "=r"(a) : "l"(p));
    return a;
}
__device__ __forceinline__ void cp_async16(u32 dst, const void* src) {
    asm volatile("cp.async.cg.shared.global [%0], [%1], 16;" :: "r"(dst), "l"(src) : "memory");
}
__device__ __forceinline__ void cp_commit() {
    asm volatile("cp.async.commit_group;" ::: "memory");
}
__device__ __forceinline__ void cp_wait1() {
    asm volatile("cp.async.wait_group 1;" ::: "memory");
}
__device__ __forceinline__ void ldsm_x4(u32* r, u32 addr) {
    asm volatile("ldmatrix.sync.aligned.m8n8.x4.shared.b16 {%0,%1,%2,%3}, [%4];"
                 : "=r"(r[0]), "=r"(r[1]), "=r"(r[2]), "=r"(r[3]) : "r"(addr));
}
__device__ __forceinline__ void mma16816(float* c, const u32* a, const u32* b) {
    asm volatile(
        "mma.sync.aligned.m16n8k16.row.col.f32.bf16.bf16.f32 "
        "{%0,%1,%2,%3}, {%4,%5,%6,%7}, {%8,%9}, {%0,%1,%2,%3};"
        : "+f"(c[0]), "+f"(c[1]), "+f"(c[2]), "+f"(c[3])
        : "r"(a[0]), "r"(a[1]), "r"(a[2]), "r"(a[3]), "r"(b[0]), "r"(b[1]));
}

// hi/lo split of 8 floats -> two packed uint4 of bf16
__device__ __forceinline__ void cvt8_split(float4 f0, float4 f1, uint4& hiw, uint4& low) {
    float v[8] = { f0.x, f0.y, f0.z, f0.w, f1.x, f1.y, f1.z, f1.w };
    unsigned short h[8], l[8];
#pragma unroll
    for (int k = 0; k < 8; ++k) {
        __nv_bfloat16 hb = __float2bfloat16(v[k]);
        __nv_bfloat16 lb = __float2bfloat16(v[k] - __bfloat162float(hb));
        h[k] = *(unsigned short*)&hb;
        l[k] = *(unsigned short*)&lb;
    }
    hiw.x = (u32)h[0] | ((u32)h[1] << 16); hiw.y = (u32)h[2] | ((u32)h[3] << 16);
    hiw.z = (u32)h[4] | ((u32)h[5] << 16); hiw.w = (u32)h[6] | ((u32)h[7] << 16);
    low.x = (u32)l[0] | ((u32)l[1] << 16); low.y = (u32)l[2] | ((u32)l[3] << 16);
    low.z = (u32)l[4] | ((u32)l[5] << 16); low.w = (u32)l[6] | ((u32)l[7] << 16);
}

// =====================================================================
// conv_split_rm: fp32 [rows, K] -> split-bf16 row-major [rows, 3K]
// =====================================================================
__global__ void conv_split_rm(const float* __restrict__ src, unsigned short* __restrict__ dst,
                              int K, int total, int a_mode)
{
    int t = blockIdx.x * blockDim.x + threadIdx.x;
    if (t >= total) return;
    int kg = t % (K >> 3);
    int r  = t / (K >> 3);
    const float4* p = (const float4*)(src + (size_t)r * K + kg * 8);
    float v[8];
    float4 f0 = __ldg(p), f1 = __ldg(p + 1);
    v[0]=f0.x; v[1]=f0.y; v[2]=f0.z; v[3]=f0.w;
    v[4]=f1.x; v[5]=f1.y; v[6]=f1.z; v[7]=f1.w;
    unsigned short o[24];
#pragma unroll
    for (int k = 0; k < 8; ++k) {
        __nv_bfloat16 hi = __float2bfloat16(v[k]);
        __nv_bfloat16 lo = __float2bfloat16(v[k] - __bfloat162float(hi));
        unsigned short hs = *(unsigned short*)&hi;
        unsigned short ls = *(unsigned short*)&lo;
        o[3*k+0] = hs;
        o[3*k+1] = a_mode ? ls : hs;
        o[3*k+2] = a_mode ? hs : ls;
    }
    unsigned short* d = dst + (size_t)r * 3 * K + (size_t)kg * 24;
    ((uint4*)d)[0] = ((uint4*)o)[0];
    ((uint4*)d)[1] = ((uint4*)o)[1];
    ((uint4*)d)[2] = ((uint4*)o)[2];
}

// =====================================================================
// bf16 tensor-core GEMM (unchanged, passing): C = A @ W^T + bias
// =====================================================================
__global__ void __launch_bounds__(256, 1) gemm_bf16_tc(
    const unsigned short* __restrict__ A, const unsigned short* __restrict__ W,
    const float* __restrict__ bias, float* __restrict__ C, int Keff)
{
    __shared__ __align__(1024) char buf[3][16384];

    const int tid  = threadIdx.x;
    const int wid  = tid >> 5;
    const int lane = tid & 31;
    const int warp_m = wid & 1;
    const int warp_n = wid >> 1;
    const int m0 = blockIdx.y * 128;
    const int n0 = blockIdx.x * 128;
    const u32 sbase = smem_u32(buf);
    const size_t strideB = (size_t)Keff * 2;
    const int niter = Keff / 32;

    float c[4][4][4];
#pragma unroll
    for (int i = 0; i < 4; ++i)
#pragma unroll
        for (int j = 0; j < 4; ++j)
#pragma unroll
            for (int q = 0; q < 4; ++q) c[i][j][q] = 0.f;

    const int rowL = tid >> 2;
    const int uL   = tid & 3;

#pragma unroll
    for (int s = 0; s < 2; ++s) {
        u32 ab = sbase + s * 16384;
#pragma unroll
        for (int q = 0; q < 2; ++q) {
            int row = rowL + q * 64;
            int p = uL ^ ((row >> 1) & 3);
            cp_async16(ab + row * 64 + p * 16,
                       (const char*)A + (size_t)(m0 + row) * strideB + (size_t)s * 64 + uL * 16);
            cp_async16(ab + 8192 + row * 64 + p * 16,
                       (const char*)W + (size_t)(n0 + row) * strideB + (size_t)s * 64 + uL * 16);
        }
        cp_commit();
    }

    for (int i = 0; i < niter; ++i) {
        cp_wait1();
        __syncthreads();

        if (i + 2 < niter) {
            u32 ab = sbase + ((i + 2) % 3) * 16384;
#pragma unroll
            for (int q = 0; q < 2; ++q) {
                int row = rowL + q * 64;
                int p = uL ^ ((row >> 1) & 3);
                cp_async16(ab + row * 64 + p * 16,
                           (const char*)A + (size_t)(m0 + row) * strideB + (size_t)(i + 2) * 64 + uL * 16);
                cp_async16(ab + 8192 + row * 64 + p * 16,
                           (const char*)W + (size_t)(n0 + row) * strideB + (size_t)(i + 2) * 64 + uL * 16);
            }
        }
        cp_commit();

        u32 abase = sbase + (i % 3) * 16384;
        u32 bbase = abase + 8192;
        const int mi = lane >> 3;
        const int rl = lane & 7;
#pragma unroll
        for (int h = 0; h < 2; ++h) {
            u32 afr[4][4];
#pragma unroll
            for (int mt = 0; mt < 4; ++mt) {
                int row = warp_m * 64 + mt * 16 + (mi & 1) * 8 + rl;
                int u = 2 * h + (mi >> 1);
                int p = u ^ ((row >> 1) & 3);
                ldsm_x4(afr[mt], abase + row * 64 + p * 16);
            }
            u32 bfr[4][2];
#pragma unroll
            for (int pp = 0; pp < 2; ++pp) {
                int j = pp * 2 + (mi >> 1);
                int row = warp_n * 32 + j * 8 + rl;
                int u = 2 * h + (mi & 1);
                int p = u ^ ((row >> 1) & 3);
                u32 r4[4];
                ldsm_x4(r4, bbase + row * 64 + p * 16);
                bfr[pp*2][0] = r4[0]; bfr[pp*2][1] = r4[1];
                bfr[pp*2+1][0] = r4[2]; bfr[pp*2+1][1] = r4[3];
            }
#pragma unroll
            for (int mt = 0; mt < 4; ++mt)
#pragma unroll
                for (int nt = 0; nt < 4; ++nt)
                    mma16816(c[mt][nt], afr[mt], bfr[nt]);
        }
        __syncthreads();
    }

    const int mwb = m0 + warp_m * 64;
    const int nwb = n0 + warp_n * 32;
#pragma unroll
    for (int mt = 0; mt < 4; ++mt) {
#pragma unroll
        for (int nt = 0; nt < 4; ++nt) {
            int m = mwb + mt * 16 + (lane >> 2);
            int n = nwb + nt * 8 + (lane & 3) * 2;
            float bx = __ldg(bias + n), by = __ldg(bias + n + 1);
            float2 o0 = { c[mt][nt][0] + bx, c[mt][nt][1] + by };
            float2 o1 = { c[mt][nt][2] + bx, c[mt][nt][3] + by };
            *(float2*)(C + (size_t)m * G3 + n) = o0;
            *(float2*)(C + (size_t)(m + 8) * G3 + n) = o1;
        }
    }
}

// =====================================================================
// grid barrier
// =====================================================================
__device__ __forceinline__ void grid_barrier_dev() {
    __syncthreads();
    if (threadIdx.x == 0) {
        __threadfence();
        unsigned gen = g_gen;
        if (atomicAdd(&g_count, 1u) == (unsigned)(gridDim.x - 1)) {
            g_count = 0;
            __threadfence();
            g_gen = gen + 1;
        } else {
            while (g_gen == gen) { }
        }
        __threadfence();
    }
    __syncthreads();
}

// =====================================================================
// Tensor-core GRU recurrence. 128 persistent CTAs x 256 threads.
// Per CTA: 8 units -> 24 gate rows. Per step: gh[16,24] = h @ w_slice^T
// via mma.m16n8k16 bf16 split-precision (hh + lh + hl), f32 accum.
// w_hh hi/lo resident in SMEM all 64 steps; h re-staged+split each step.
// SMEM layout (bytes):
//   w_hi    0 .. 49152   [32 chunks][24 rows][64B]  (chunk stride 1536)
//   w_lo    49152 .. 98304
//   h_hi    98304 .. 131072 [32][16][64]            (chunk stride 1024)
//   h_lo    131072 .. 163840
//   red     163840 .. 176128 [8 warps][3 tiles][32 lanes][4 f32]
// =====================================================================
#define RCTA 128
#define REC_SMEM_TC 176128
#define WHI_OFF 0
#define WLO_OFF 49152
#define HHI_OFF 98304
#define HLO_OFF 131072
#define RED_OFF 163840

__global__ void __launch_bounds__(256, 1) gru_rec_tc(
    const float* __restrict__ w_hh, const float* __restrict__ b_hh,
    const float* __restrict__ gates, float* __restrict__ seq_out,
    int write_seq)
{
    extern __shared__ __align__(1024) char sm[];
    const u32 sb = smem_u32(sm);

    const int tid  = threadIdx.x;
    const int wid  = tid >> 5;
    const int lane = tid & 31;
    const int mi = lane >> 3;
    const int rl = lane & 7;
    const int ubase = blockIdx.x * 8;

    // ---- convert w_hh slice to split bf16 in SMEM (once) ----
    // rows r = ul*3 + g ; source row g*HH + ubase + ul
    for (int idx = tid; idx < 24 * 128; idx += 256) {
        int r = idx >> 7;           // 0..23
        int q = idx & 127;          // 8-float group along k
        int ulcl = r / 3, g = r - ulcl * 3;
        const float4* src = (const float4*)(w_hh + (size_t)(g * HH + ubase + ulcl) * HH + q * 8);
        float4 f0 = __ldg(src), f1 = __ldg(src + 1);
        uint4 hiw, low;
        cvt8_split(f0, f1, hiw, low);
        int c = q >> 2, u = q & 3;
        u32 off = (u32)(c * 1536 + r * 64 + ((u ^ ((r >> 1) & 3)) << 4));
        *(uint4*)(sm + WHI_OFF + off) = hiw;
        *(uint4*)(sm + WLO_OFF + off) = low;
    }

    // ---- zero h0 (buffer 0) across the grid ----
    {
        int idx = blockIdx.x * 256 + tid;
        if (idx < BQ * HH) g_hbuf[0][idx] = 0.f;
    }

    // ---- epilogue constants (tid < 128: unit ul_ep, batch b_ep) ----
    const int ul_ep = tid >> 4;
    const int b_ep  = tid & 15;
    const int u_ep  = ubase + ul_ep;
    float bhr = 0.f, bhz = 0.f, bhn = 0.f;
    if (tid < 128) {
        bhr = b_hh[u_ep];
        bhz = b_hh[HH + u_ep];
        bhn = b_hh[2 * HH + u_ep];
    }

    const float* red = (const float*)(sm + RED_OFF);

    grid_barrier_dev();   // zeros + (cta-local) weights visible

    for (int t = 0; t < TT; ++t) {
        const float* hsrc = g_hbuf[t & 1];
        float* hdst = g_hbuf[(t + 1) & 1];

        // early loads for the epilogue (long slack across the mma phase)
        float gxr = 0.f, gxz = 0.f, gxn = 0.f, hp = 0.f;
        if (tid < 128) {
            const float* gp = gates + (size_t)(b_ep * TT + t) * G3 + u_ep;
            gxr = __ldg(gp);
            gxz = __ldg(gp + HH);
            gxn = __ldg(gp + 2 * HH);
            hp  = __ldcg(hsrc + b_ep * HH + u_ep);
        }

        // ---- stage h: fp32 from L2 -> split bf16 smem (2048 units/8 iters) ----
        for (int idx = tid; idx < 16 * 128; idx += 256) {
            int r = idx >> 7;       // batch
            int q = idx & 127;
            const float4* src = (const float4*)(hsrc + (size_t)r * HH + q * 8);
            float4 f0 = __ldcg(src), f1 = __ldcg(src + 1);
            uint4 hiw, low;
            cvt8_split(f0, f1, hiw, low);
            int c = q >> 2, u = q & 3;
            u32 off = (u32)(c * 1024 + r * 64 + ((u ^ ((r >> 1) & 3)) << 4));
            *(uint4*)(sm + HHI_OFF + off) = hiw;
            *(uint4*)(sm + HLO_OFF + off) = low;
        }
        __syncthreads();

        // ---- mma phase: warp owns k chunks 4*wid .. 4*wid+3 ----
        float cacc[3][4];
#pragma unroll
        for (int nt = 0; nt < 3; ++nt)
#pragma unroll
            for (int q = 0; q < 4; ++q) cacc[nt][q] = 0.f;

#pragma unroll
        for (int cc = 0; cc < 4; ++cc) {
            int ch = wid * 4 + cc;
            u32 ha = sb + HHI_OFF + ch * 1024;
            u32 la = sb + HLO_OFF + ch * 1024;
            u32 wa = sb + WHI_OFF + ch * 1536;
            u32 wl = sb + WLO_OFF + ch * 1536;
#pragma unroll
            for (int h2 = 0; h2 < 2; ++h2) {
                int arow = ((mi & 1) << 3) + rl;
                int au = 2 * h2 + (mi >> 1);
                u32 aoff = (u32)(arow * 64 + ((au ^ ((arow >> 1) & 3)) << 4));
                u32 ahi[4], alo[4];
                ldsm_x4(ahi, ha + aoff);
                ldsm_x4(alo, la + aoff);

                int b01row = ((mi >> 1) << 3) + rl;
                int bu = 2 * h2 + (mi & 1);
                u32 b01off = (u32)(b01row * 64 + ((bu ^ ((b01row >> 1) & 3)) << 4));
                int b2row = 16 + rl;
                u32 b2off = (u32)(b2row * 64 + ((bu ^ ((b2row >> 1) & 3)) << 4));
                u32 bh01[4], bh2[4], bl01[4], bl2[4];
                ldsm_x4(bh01, wa + b01off);
                ldsm_x4(bh2,  wa + b2off);
                ldsm_x4(bl01, wl + b01off);
                ldsm_x4(bl2,  wl + b2off);

                u32 bt0[2] = { bh01[0], bh01[1] };
                u32 bt1[2] = { bh01[2], bh01[3] };
                u32 bt2[2] = { bh2[0],  bh2[1]  };
                u32 lt0[2] = { bl01[0], bl01[1] };
                u32 lt1[2] = { bl01[2], bl01[3] };
                u32 lt2[2] = { bl2[0],  bl2[1]  };

                mma16816(cacc[0], ahi, bt0);
                mma16816(cacc[1], ahi, bt1);
                mma16816(cacc[2], ahi, bt2);
                mma16816(cacc[0], alo, bt0);
                mma16816(cacc[1], alo, bt1);
                mma16816(cacc[2], alo, bt2);
                mma16816(cacc[0], ahi, lt0);
                mma16816(cacc[1], ahi, lt1);
                mma16816(cacc[2], ahi, lt2);
            }
        }

        // ---- store partial frags, reduce across 8 warps ----
#pragma unroll
        for (int nt = 0; nt < 3; ++nt) {
            float4 v = { cacc[nt][0], cacc[nt][1], cacc[nt][2], cacc[nt][3] };
            *(float4*)(sm + RED_OFF + (size_t)(((wid * 3 + nt) * 32 + lane) << 4)) = v;
        }
        __syncthreads();

        // ---- epilogue: tid<128 -> (unit, batch) ----
        if (tid < 128) {
            float gh[3];
#pragma unroll
            for (int g = 0; g < 3; ++g) {
                int j = ul_ep * 3 + g;       // gate row within 24
                int tile = j >> 3;
                int col = j & 7;
                int ln = (b_ep & 7) * 4 + (col >> 1);
                int rg = (col & 1) + 2 * (b_ep >> 3);
                float s = 0.f;
#pragma unroll
                for (int w8 = 0; w8 < 8; ++w8)
                    s += red[((w8 * 3 + tile) * 32 + ln) * 4 + rg];
                gh[g] = s;
            }
            float rr = 1.f / (1.f + __expf(-(gxr + gh[0] + bhr)));
            float zz = 1.f / (1.f + __expf(-(gxz + gh[1] + bhz)));
            float nn = tanhf(gxn + rr * (gh[2] + bhn));
            float hv = (1.f - zz) * nn + zz * hp;
            __stcg(&hdst[b_ep * HH + u_ep], hv);
            if (write_seq)
                seq_out[(size_t)(b_ep * TT + t) * HH + u_ep] = hv;
        }

        grid_barrier_dev();
    }
}

// =====================================================================
// Decoder (unchanged)
// =====================================================================
__global__ void __launch_bounds__(256) decoder_kernel(
    const float* __restrict__ h, const float* __restrict__ dw,
    const float* __restrict__ db, float* __restrict__ out)
{
    extern __shared__ __align__(16) float sh[];
    const int tid = threadIdx.x;
    for (int i = tid; i < BQ * HH / 4; i += 256)
        ((float4*)sh)[i] = ((const float4*)h)[i];
    __syncthreads();

    const int w = tid >> 5, lane = tid & 31;
#pragma unroll 1
    for (int i = 0; i < 4; ++i) {
        int n = blockIdx.x * 32 + w * 4 + i;
        float acc[16];
#pragma unroll
        for (int b = 0; b < 16; ++b) acc[b] = 0.f;
#pragma unroll
        for (int it = 0; it < 8; ++it) {
            int kq = it * 32 + lane;
            float4 wv = __ldg(((const float4*)(dw + (size_t)n * HH)) + kq);
#pragma unroll
            for (int b = 0; b < 16; ++b) {
                float4 hv = *(((const float4*)(sh + b * HH)) + kq);
                acc[b] += wv.x * hv.x + wv.y * hv.y + wv.z * hv.z + wv.w * hv.w;
            }
        }
        float myv = 0.f;
#pragma unroll
        for (int b = 0; b < 16; ++b) {
            float v = acc[b];
            v += __shfl_xor_sync(0xffffffffu, v, 16);
            v += __shfl_xor_sync(0xffffffffu, v, 8);
            v += __shfl_xor_sync(0xffffffffu, v, 4);
            v += __shfl_xor_sync(0xffffffffu, v, 2);
            v += __shfl_xor_sync(0xffffffffu, v, 1);
            if (lane == b) myv = v;
        }
        if (lane < 16) out[(size_t)lane * NNDIM + n] = myv + __ldg(db + n);
    }
}

// =====================================================================
extern "C" void kernel_launch(void* const* d_in, const int* in_sizes, int n_in,
                              void* d_out, int out_size)
{
    const float* x      = (const float*)d_in[0];
    const float* w_ih0  = (const float*)d_in[1];
    const float* w_hh0  = (const float*)d_in[2];
    const float* b_ih0  = (const float*)d_in[3];
    const float* b_hh0  = (const float*)d_in[4];
    const float* w_ih1  = (const float*)d_in[5];
    const float* w_hh1  = (const float*)d_in[6];
    const float* b_ih1  = (const float*)d_in[7];
    const float* b_hh1  = (const float*)d_in[8];
    const float* dec_w  = (const float*)d_in[9];
    const float* dec_b  = (const float*)d_in[10];
    float* out = (float*)d_out;

    float *gates, *seq, *hbuf;
    unsigned short *wcvt, *acvt;
    cudaGetSymbolAddress((void**)&gates, g_gates);
    cudaGetSymbolAddress((void**)&seq,   g_seq);
    cudaGetSymbolAddress((void**)&hbuf,  g_hbuf);
    cudaGetSymbolAddress((void**)&wcvt,  g_wcvt);
    cudaGetSymbolAddress((void**)&acvt,  g_acvt);

    cudaFuncSetAttribute(gru_rec_tc,
                         cudaFuncAttributeMaxDynamicSharedMemorySize, REC_SMEM_TC);
    cudaFuncSetAttribute(decoder_kernel,
                         cudaFuncAttributeMaxDynamicSharedMemorySize, BQ * HH * 4);

    dim3 ggrid(G3 / 128, (BQ * TT) / 128);   // (24, 8)

    // ---- layer 0 ----
    {
        int K = NNDIM;
        int totW = G3 * (K / 8), totA = BQ * TT * (K / 8);
        conv_split_rm<<<(totW + 255) / 256, 256>>>(w_ih0, wcvt, K, totW, 0);
        conv_split_rm<<<(totA + 255) / 256, 256>>>(x,     acvt, K, totA, 1);
        gemm_bf16_tc<<<ggrid, 256>>>(acvt, wcvt, b_ih0, gates, 3 * K);
    }
    gru_rec_tc<<<RCTA, 256, REC_SMEM_TC>>>(w_hh0, b_hh0, gates, seq, 1);

    // ---- layer 1 ----
    {
        int K = HH;
        int totW = G3 * (K / 8), totA = BQ * TT * (K / 8);
        conv_split_rm<<<(totW + 255) / 256, 256>>>(w_ih1, wcvt, K, totW, 0);
        conv_split_rm<<<(totA + 255) / 256, 256>>>(seq,   acvt, K, totA, 1);
        gemm_bf16_tc<<<ggrid, 256>>>(acvt, wcvt, b_ih1, gates, 3 * K);
    }
    gru_rec_tc<<<RCTA, 256, REC_SMEM_TC>>>(w_hh1, b_hh1, gates, seq, 0);

    // ---- decoder ----
    decoder_kernel<<<NNDIM / 32, 256, BQ * HH * 4>>>(hbuf, dec_w, dec_b, out);
}